// round 4
// baseline (speedup 1.0000x reference)
#include <cuda_runtime.h>
#include <math.h>

#define BB 4
#define NN 2048
#define KNN 48
#define NRBF 16
#define NPE 16
#define EDGE_C 128
#define PE_IN 66
#define MAXREL 32
#define ROWS_PER_CTA 16
#define EDGES_PER_WARP 16

// scratch (no cudaMalloc allowed)
__device__ float4 g_X4[BB * NN];              // xyz = masked coords, w = mask
__device__ float  g_PW[PE_IN * EDGE_C];       // (pe_w[d]+pe_b) @ edge_w[0:16]
__device__ float4 g_E4[BB * NN * KNN];        // per-edge (D, dc, tb, -)

// f32x2 packed helpers
__device__ __forceinline__ unsigned long long pk2(float a, float b) {
    unsigned long long r;
    asm("mov.b64 %0, {%1, %2};" : "=l"(r) : "f"(a), "f"(b));
    return r;
}
__device__ __forceinline__ void unpk2(unsigned long long v, float& a, float& b) {
    asm("mov.b64 {%0, %1}, %2;" : "=f"(a), "=f"(b) : "l"(v));
}
__device__ __forceinline__ unsigned long long fma2(unsigned long long a,
                                                   unsigned long long b,
                                                   unsigned long long c) {
    unsigned long long d;
    asm("fma.rn.f32x2 %0, %1, %2, %3;" : "=l"(d) : "l"(a), "l"(b), "l"(c));
    return d;
}

// ---------------------------------------------------------------------------
// Kernel 1: gather center-atom coords, apply mask, pack mask into .w
// ---------------------------------------------------------------------------
__global__ void gather_kernel(const float* __restrict__ coords,
                              const float* __restrict__ mask,
                              const int* __restrict__ t2c) {
    int t = blockIdx.x * blockDim.x + threadIdx.x;   // b*N + n
    if (t >= BB * NN) return;
    int b = t / NN;
    int a = t2c[t];
    float m = mask[t];
    const float* src = coords + ((size_t)b * NN + a) * 3;
    g_X4[t] = make_float4(src[0] * m, src[1] * m, src[2] * m, m);
}

// ---------------------------------------------------------------------------
// Kernel 2: positional table PW[d][c] = sum_p (pe_w[d,p]+pe_b[p])*edge_w[p,c]
// ---------------------------------------------------------------------------
__global__ void pw_kernel(const float* __restrict__ pe_w,
                          const float* __restrict__ pe_b,
                          const float* __restrict__ edge_w) {
    int d = blockIdx.x;      // 0..65
    int c = threadIdx.x;     // 0..127
    float acc = 0.f;
#pragma unroll
    for (int p = 0; p < NPE; p++)
        acc += (pe_w[d * NPE + p] + pe_b[p]) * edge_w[p * EDGE_C + c];
    g_PW[d * EDGE_C + c] = acc;
}

// ---------------------------------------------------------------------------
// Kernel 3: KNN select. One CTA (256 thr) handles 16 rows, X tile in SMEM.
// Radix select on (f32bits(D_adjust)<<32 | j) keys with warp-aggregated hist.
// Emits E_idx, D_neighbors, and per-edge scalars (D, dc, tb) to g_E4.
// ---------------------------------------------------------------------------
__global__ __launch_bounds__(256)
void knn_kernel(const float* __restrict__ bonds,
                const int*   __restrict__ resi,
                const int*   __restrict__ lig,
                float* __restrict__ outIdx,
                float* __restrict__ outD) {
    const int tid  = threadIdx.x;
    const int lane = tid & 31;
    const int wid  = tid >> 5;
    const int row0 = blockIdx.x * ROWS_PER_CTA;
    const int b    = row0 / NN;           // ROWS_PER_CTA divides NN

    __shared__ float4 sX[NN];             // 32KB batch coord tile
    __shared__ int    sHist[256];
    __shared__ int    sWs[8];
    __shared__ float  sRed[8];
    __shared__ int    sSelDig, sBelow, sCnt, sNum;
    __shared__ unsigned long long sKth;
    __shared__ unsigned long long sCand[KNN];

    for (int idx = tid; idx < NN; idx += 256) sX[idx] = g_X4[b * NN + idx];
    __syncthreads();

    for (int r = 0; r < ROWS_PER_CTA; r++) {
        const int row = row0 + r;
        const int i   = row - b * NN;
        const float4 xi = sX[i];

        // ---- distances: 8 neighbors per thread ----
        float dloc[8], m2loc[8];
        float vmax = 0.f;
#pragma unroll
        for (int s = 0; s < 8; s++) {
            int j = tid + s * 256;
            float4 xj = sX[j];
            float dx = xi.x - xj.x;
            float dy = xi.y - xj.y;
            float dz = xi.z - xj.z;
            float m2 = xi.w * xj.w;
            float D  = m2 * sqrtf(dx * dx + dy * dy + dz * dz + 1e-6f);
            dloc[s] = D; m2loc[s] = m2;
            vmax = fmaxf(vmax, D);
        }
#pragma unroll
        for (int o = 16; o; o >>= 1) vmax = fmaxf(vmax, __shfl_xor_sync(0xffffffffu, vmax, o));
        if (lane == 0) sRed[wid] = vmax;
        __syncthreads();
        float Dmax = sRed[0];
#pragma unroll
        for (int w = 1; w < 8; w++) Dmax = fmaxf(Dmax, sRed[w]);

        // ---- keys (asc order == JAX top_k order incl. ties) ----
        unsigned long long keys[8];
#pragma unroll
        for (int s = 0; s < 8; s++) {
            int j = tid + s * 256;
            float Dadj = dloc[s] + (1.f - m2loc[s]) * Dmax;
            keys[s] = ((unsigned long long)__float_as_uint(Dadj) << 32) | (unsigned int)j;
        }

        // ---- radix select the KNN-th smallest key ----
        unsigned long long pref = 0;
        int krank = KNN;
        bool resolved = false;
        for (int shift = 56; shift >= 0; shift -= 8) {
            sHist[tid] = 0;
            __syncthreads();
            unsigned long long hm = (shift == 56) ? 0ULL : (~0ULL << (shift + 8));
#pragma unroll
            for (int s = 0; s < 8; s++) {
                unsigned long long key = keys[s];
                bool act = ((key & hm) == pref);
                unsigned dig = act ? (unsigned)((key >> shift) & 255) : 0xffffffffu;
                unsigned mm = __match_any_sync(0xffffffffu, dig);
                if (act && lane == (__ffs(mm) - 1))
                    atomicAdd(&sHist[dig], __popc(mm));
            }
            __syncthreads();
            int v = sHist[tid];
            int sc = v;
#pragma unroll
            for (int o = 1; o < 32; o <<= 1) {
                int n = __shfl_up_sync(0xffffffffu, sc, o);
                if (lane >= o) sc += n;
            }
            if (lane == 31) sWs[wid] = sc;
            __syncthreads();
            if (wid == 0) {
                int wv = (lane < 8) ? sWs[lane] : 0;
#pragma unroll
                for (int o = 1; o < 8; o <<= 1) {
                    int n = __shfl_up_sync(0xffffffffu, wv, o);
                    if (lane >= o) wv += n;
                }
                if (lane < 8) sWs[lane] = wv;
            }
            __syncthreads();
            int cum = sc + (wid ? sWs[wid - 1] : 0);
            if (cum >= krank && cum - v < krank) { sSelDig = tid; sBelow = cum - v; sCnt = v; }
            __syncthreads();
            pref |= ((unsigned long long)sSelDig << shift);
            krank -= sBelow;
            if (sCnt == 1) {
                unsigned long long hm2 = (shift == 0) ? ~0ULL : (~0ULL << shift);
#pragma unroll
                for (int s = 0; s < 8; s++)
                    if ((keys[s] & hm2) == pref) sKth = keys[s];
                resolved = true;
            }
            __syncthreads();
            if (resolved) break;
        }
        unsigned long long kth = resolved ? sKth : pref;

        // ---- compact exactly-KNN keys <= kth (keys unique) ----
        if (tid == 0) sNum = 0;
        __syncthreads();
#pragma unroll
        for (int s = 0; s < 8; s++) {
            if (keys[s] <= kth) {
                int p = atomicAdd(&sNum, 1);
                sCand[p] = keys[s];
            }
        }
        __syncthreads();

        // ---- rank by counting, emit outputs + edge scalars ----
        if (tid < KNN) {
            unsigned long long kk = sCand[tid];
            int rank = 0;
#pragma unroll 4
            for (int m = 0; m < KNN; m++) rank += (sCand[m] < kk);
            int   j = (int)(kk & 0xffffffffu);
            float D = __uint_as_float((unsigned int)(kk >> 32));
            int off = resi[row] - resi[b * NN + j];
            int dc = off + MAXREL;
            dc = dc < 0 ? 0 : (dc > 2 * MAXREL ? 2 * MAXREL : dc);
            float tb = bonds[(size_t)row * NN + j];
            tb = (lig[row] | lig[b * NN + j]) ? tb : 0.f;
            outIdx[(size_t)row * KNN + rank] = (float)j;
            outD  [(size_t)row * KNN + rank] = D;
            g_E4  [(size_t)row * KNN + rank] = make_float4(D, (float)dc, tb, 0.f);
        }
        __syncthreads();   // protect shared reuse across rows
    }
}

// ---------------------------------------------------------------------------
// Kernel 4: per-edge embed + layernorm. One warp per edge (x16 edges/warp).
// Lane owns 4 contiguous channels; W2 lives in registers as packed f32x2.
// ---------------------------------------------------------------------------
__global__ __launch_bounds__(256)
void edge_kernel(const float* __restrict__ edge_w,
                 const float* __restrict__ ln_g,
                 const float* __restrict__ ln_b,
                 float* __restrict__ outE) {
    const int tid  = threadIdx.x;
    const int lane = tid & 31;
    const int wid  = tid >> 5;

    // stage weights into registers (channels 4*lane .. 4*lane+3)
    unsigned long long w2a[NRBF], w2b[NRBF];
#pragma unroll
    for (int r = 0; r < NRBF; r++) {
        const float4 v = *(const float4*)(edge_w + (NPE + r) * EDGE_C + 4 * lane);
        w2a[r] = pk2(v.x, v.y);
        w2b[r] = pk2(v.z, v.w);
    }
    const float4 w3 = *(const float4*)(edge_w + (NPE + NRBF) * EDGE_C + 4 * lane);
    const float4 lg = *(const float4*)(ln_g + 4 * lane);
    const float4 lb = *(const float4*)(ln_b + 4 * lane);

    const float mu_r = 2.f + (20.f / 15.f) * (float)(lane & 15);

    size_t edge = (size_t)blockIdx.x * (8 * EDGES_PER_WARP) + (size_t)wid * EDGES_PER_WARP;
#pragma unroll 2
    for (int e = 0; e < EDGES_PER_WARP; e++, edge++) {
        float4 sc = g_E4[edge];
        float D  = sc.x;
        int   dc = (int)sc.y;
        float tb = sc.z;

        float tt = (D - mu_r) * (1.f / 1.25f);
        float myrbf = expf(-tt * tt);

        const float4 pw = *(const float4*)(g_PW + dc * EDGE_C + 4 * lane);
        unsigned long long acc0 = pk2(fmaf(tb, w3.x, pw.x), fmaf(tb, w3.y, pw.y));
        unsigned long long acc1 = pk2(fmaf(tb, w3.z, pw.z), fmaf(tb, w3.w, pw.w));
#pragma unroll
        for (int r = 0; r < NRBF; r++) {
            float rb = __shfl_sync(0xffffffffu, myrbf, r);
            unsigned long long rb2 = pk2(rb, rb);
            acc0 = fma2(rb2, w2a[r], acc0);
            acc1 = fma2(rb2, w2b[r], acc1);
        }
        float a0, a1, a2, a3;
        unpk2(acc0, a0, a1);
        unpk2(acc1, a2, a3);

        float s1 = (a0 + a1) + (a2 + a3);
#pragma unroll
        for (int o = 16; o; o >>= 1) s1 += __shfl_xor_sync(0xffffffffu, s1, o);
        float mean = s1 * (1.f / 128.f);
        float d0 = a0 - mean, d1 = a1 - mean, d2 = a2 - mean, d3 = a3 - mean;
        float s2 = (d0 * d0 + d1 * d1) + (d2 * d2 + d3 * d3);
#pragma unroll
        for (int o = 16; o; o >>= 1) s2 += __shfl_xor_sync(0xffffffffu, s2, o);
        float rstd = rsqrtf(s2 * (1.f / 128.f) + 1e-5f);

        float4 o4;
        o4.x = d0 * rstd * lg.x + lb.x;
        o4.y = d1 * rstd * lg.y + lb.y;
        o4.z = d2 * rstd * lg.z + lb.z;
        o4.w = d3 * rstd * lg.w + lb.w;
        *(float4*)(outE + edge * EDGE_C + 4 * lane) = o4;
    }
}

// ---------------------------------------------------------------------------
extern "C" void kernel_launch(void* const* d_in, const int* in_sizes, int n_in,
                              void* d_out, int out_size) {
    const float* coords = (const float*)d_in[0];
    const float* mask   = (const float*)d_in[1];
    const float* bonds  = (const float*)d_in[2];
    const float* pe_w   = (const float*)d_in[3];
    const float* pe_b   = (const float*)d_in[4];
    const float* edge_w = (const float*)d_in[5];
    const float* ln_g   = (const float*)d_in[6];
    const float* ln_b   = (const float*)d_in[7];
    const int*   t2c    = (const int*)d_in[8];
    const int*   resi   = (const int*)d_in[9];
    // d_in[10] = asym_id (unused: chain labels forced to zero in reference)
    const int*   lig    = (const int*)d_in[11];

    float* out    = (float*)d_out;
    float* outE   = out;                                        // B*N*K*128
    float* outIdx = out + (size_t)BB * NN * KNN * EDGE_C;       // B*N*K
    float* outD   = outIdx + (size_t)BB * NN * KNN;             // B*N*K

    gather_kernel<<<(BB * NN + 255) / 256, 256>>>(coords, mask, t2c);
    pw_kernel<<<PE_IN, EDGE_C>>>(pe_w, pe_b, edge_w);
    knn_kernel<<<BB * NN / ROWS_PER_CTA, 256>>>(bonds, resi, lig, outIdx, outD);
    edge_kernel<<<BB * NN * KNN / (8 * EDGES_PER_WARP), 256>>>(edge_w, ln_g, ln_b, outE);
}

// round 7
// speedup vs baseline: 1.7897x; 1.7897x over previous
#include <cuda_runtime.h>
#include <math.h>

#define BB 4
#define NN 2048
#define KNN 48
#define NRBF 16
#define NPE 16
#define EDGE_C 128
#define PE_IN 66
#define MAXREL 32
#define ROWS_PER_CTA 4
#define NBIN 2048
#define CAND_CAP 768
#define EDGES_PER_WARP 16

// scratch (no cudaMalloc allowed)
__device__ float4 g_X4[BB * NN];              // xyz = masked coords, w = mask
__device__ float  g_PW[PE_IN * EDGE_C];       // (pe_w[d]+pe_b) @ edge_w[0:16]
__device__ float4 g_E4[BB * NN * KNN];        // per-edge (D, dc, tb, -)

// f32x2 packed helpers
__device__ __forceinline__ unsigned long long pk2(float a, float b) {
    unsigned long long r;
    asm("mov.b64 %0, {%1, %2};" : "=l"(r) : "f"(a), "f"(b));
    return r;
}
__device__ __forceinline__ void unpk2(unsigned long long v, float& a, float& b) {
    asm("mov.b64 {%0, %1}, %2;" : "=f"(a), "=f"(b) : "l"(v));
}
__device__ __forceinline__ unsigned long long fma2(unsigned long long a,
                                                   unsigned long long b,
                                                   unsigned long long c) {
    unsigned long long d;
    asm("fma.rn.f32x2 %0, %1, %2, %3;" : "=l"(d) : "l"(a), "l"(b), "l"(c));
    return d;
}

// ---------------------------------------------------------------------------
// Kernel 1 (fused setup): blocks 0..31 gather coords; blocks 32..64 build PW.
// ---------------------------------------------------------------------------
__global__ void setup_kernel(const float* __restrict__ coords,
                             const float* __restrict__ mask,
                             const int*   __restrict__ t2c,
                             const float* __restrict__ pe_w,
                             const float* __restrict__ pe_b,
                             const float* __restrict__ edge_w) {
    if (blockIdx.x < 32) {
        int t = blockIdx.x * 256 + threadIdx.x;   // b*N + n
        int b = t / NN;
        int a = t2c[t];
        float m = mask[t];
        const float* src = coords + ((size_t)b * NN + a) * 3;
        g_X4[t] = make_float4(src[0] * m, src[1] * m, src[2] * m, m);
    } else {
        int d = (blockIdx.x - 32) * 2 + (threadIdx.x >> 7);   // 0..65
        if (d < PE_IN) {
            int c = threadIdx.x & 127;
            float acc = 0.f;
#pragma unroll
            for (int p = 0; p < NPE; p++)
                acc += (pe_w[d * NPE + p] + pe_b[p]) * edge_w[p * EDGE_C + c];
            g_PW[d * EDGE_C + c] = acc;
        }
    }
}

// ---------------------------------------------------------------------------
// Kernel 2: KNN select. One CTA (256 thr) handles 4 rows, X tile in SMEM.
// Single-pass 2048-bin histogram on top-11 bits of f32(D_adjust) -> boundary
// bin -> compact candidates -> exact rank by 64-bit key count.
// ---------------------------------------------------------------------------
__global__ __launch_bounds__(256)
void knn_kernel(const float* __restrict__ bonds,
                const int*   __restrict__ resi,
                const int*   __restrict__ lig,
                float* __restrict__ outIdx,
                float* __restrict__ outD) {
    const int tid  = threadIdx.x;
    const int lane = tid & 31;
    const int wid  = tid >> 5;
    const int row0 = blockIdx.x * ROWS_PER_CTA;
    const int b    = row0 / NN;

    __shared__ float4 sX[NN];                       // 32 KB
    __shared__ int    sHist[NBIN];                  // 8 KB
    __shared__ unsigned long long sCand[CAND_CAP];  // 6 KB
    __shared__ float  sRed[8];
    __shared__ int    sWs[8];
    __shared__ int    sBinB, sBless, sNum;

    for (int idx = tid; idx < NN; idx += 256) sX[idx] = g_X4[b * NN + idx];
    __syncthreads();

    for (int r = 0; r < ROWS_PER_CTA; r++) {
        const int row = row0 + r;
        const int i   = row - b * NN;
        const float4 xi = sX[i];

        // ---- distances: 8 neighbors per thread ----
        float dloc[8], m2loc[8];
        float vmax = 0.f;
#pragma unroll
        for (int s = 0; s < 8; s++) {
            int j = tid + s * 256;
            float4 xj = sX[j];
            float dx = xi.x - xj.x;
            float dy = xi.y - xj.y;
            float dz = xi.z - xj.z;
            float m2 = xi.w * xj.w;
            float D  = m2 * sqrtf(dx * dx + dy * dy + dz * dz + 1e-6f);
            dloc[s] = D; m2loc[s] = m2;
            vmax = fmaxf(vmax, D);
        }
#pragma unroll
        for (int o = 16; o; o >>= 1) vmax = fmaxf(vmax, __shfl_xor_sync(0xffffffffu, vmax, o));
        if (lane == 0) sRed[wid] = vmax;
        // zero histogram while the max reduction settles
        *(int4*)(sHist + tid * 8)     = make_int4(0, 0, 0, 0);
        *(int4*)(sHist + tid * 8 + 4) = make_int4(0, 0, 0, 0);
        if (tid == 0) { sNum = 0; }
        __syncthreads();
        float Dmax = sRed[0];
#pragma unroll
        for (int w = 1; w < 8; w++) Dmax = fmaxf(Dmax, sRed[w]);

        // ---- keys (asc order == JAX top_k order incl. ties) ----
        unsigned long long keys[8];
#pragma unroll
        for (int s = 0; s < 8; s++) {
            int j = tid + s * 256;
            float Dadj = dloc[s] + (1.f - m2loc[s]) * Dmax;
            keys[s] = ((unsigned long long)__float_as_uint(Dadj) << 32) | (unsigned int)j;
        }

        // ---- histogram on top-11 bits (warp-aggregated atomics) ----
#pragma unroll
        for (int s = 0; s < 8; s++) {
            unsigned bin = (unsigned)(keys[s] >> 53);
            unsigned mm = __match_any_sync(0xffffffffu, bin);
            if (lane == (__ffs(mm) - 1))
                atomicAdd(&sHist[bin], __popc(mm));
        }
        __syncthreads();

        // ---- scan: 8 bins/thread serial + block scan of partials ----
        int psum = 0;
        int base = tid * 8;
#pragma unroll
        for (int t = 0; t < 8; t++) psum += sHist[base + t];
        int sc = psum;
#pragma unroll
        for (int o = 1; o < 32; o <<= 1) {
            int n = __shfl_up_sync(0xffffffffu, sc, o);
            if (lane >= o) sc += n;
        }
        if (lane == 31) sWs[wid] = sc;
        __syncthreads();
        if (wid == 0) {
            int wv = (lane < 8) ? sWs[lane] : 0;
#pragma unroll
            for (int o = 1; o < 8; o <<= 1) {
                int n = __shfl_up_sync(0xffffffffu, wv, o);
                if (lane >= o) wv += n;
            }
            if (lane < 8) sWs[lane] = wv;
        }
        __syncthreads();
        int excl = sc - psum + (wid ? sWs[wid - 1] : 0);
        // boundary bin: cumulative crosses KNN inside this thread's range?
        int running = excl;
#pragma unroll
        for (int t = 0; t < 8; t++) {
            int c = sHist[base + t];
            if (running < KNN && running + c >= KNN) { sBinB = base + t; sBless = running; }
            running += c;
        }
        __syncthreads();
        const unsigned binB = (unsigned)sBinB;

        // ---- compact candidates: all keys in bins <= binB ----
#pragma unroll
        for (int s = 0; s < 8; s++) {
            if ((unsigned)(keys[s] >> 53) <= binB) {
                int p = atomicAdd(&sNum, 1);
                if (p < CAND_CAP) sCand[p] = keys[s];
            }
        }
        __syncthreads();
        int num = sNum < CAND_CAP ? sNum : CAND_CAP;

        // ---- exact rank by counting (LDS broadcast inner loop), emit ----
        for (int ci = tid; ci < num; ci += 256) {
            unsigned long long kk = sCand[ci];
            int rank = 0;
            for (int m = 0; m < num; m++) rank += (sCand[m] < kk);
            if (rank < KNN) {
                int   j = (int)(kk & 0xffffffffu);
                float D = __uint_as_float((unsigned int)(kk >> 32));
                int off = resi[row] - resi[b * NN + j];
                int dc = off + MAXREL;
                dc = dc < 0 ? 0 : (dc > 2 * MAXREL ? 2 * MAXREL : dc);
                float tb = bonds[(size_t)row * NN + j];
                tb = (lig[row] | lig[b * NN + j]) ? tb : 0.f;
                outIdx[(size_t)row * KNN + rank] = (float)j;
                outD  [(size_t)row * KNN + rank] = D;
                g_E4  [(size_t)row * KNN + rank] = make_float4(D, (float)dc, tb, 0.f);
            }
        }
        __syncthreads();   // protect sHist/sCand/sNum reuse across rows
    }
}

// ---------------------------------------------------------------------------
// Kernel 3: per-edge embed + layernorm. One warp per edge; 2 edges in flight
// per iteration with next-pair prefetch. W2 register-resident as f32x2.
// ---------------------------------------------------------------------------
__global__ __launch_bounds__(256)
void edge_kernel(const float* __restrict__ edge_w,
                 const float* __restrict__ ln_g,
                 const float* __restrict__ ln_b,
                 float* __restrict__ outE) {
    const int tid  = threadIdx.x;
    const int lane = tid & 31;
    const int wid  = tid >> 5;

    // stage weights into registers (channels 4*lane .. 4*lane+3)
    unsigned long long w2a[NRBF], w2b[NRBF];
#pragma unroll
    for (int r = 0; r < NRBF; r++) {
        const float4 v = *(const float4*)(edge_w + (NPE + r) * EDGE_C + 4 * lane);
        w2a[r] = pk2(v.x, v.y);
        w2b[r] = pk2(v.z, v.w);
    }
    const float4 w3 = *(const float4*)(edge_w + (NPE + NRBF) * EDGE_C + 4 * lane);
    const float4 lg = *(const float4*)(ln_g + 4 * lane);
    const float4 lb = *(const float4*)(ln_b + 4 * lane);

    const float mu_r = 2.f + (20.f / 15.f) * (float)(lane & 15);

    const size_t e0 = (size_t)blockIdx.x * (8 * EDGES_PER_WARP) + (size_t)wid * EDGES_PER_WARP;

    // software pipeline: sc/pw for the current pair pre-loaded
    float4 scA = g_E4[e0];
    float4 scB = g_E4[e0 + 1];
    float4 pwA = *(const float4*)(g_PW + (int)scA.y * EDGE_C + 4 * lane);
    float4 pwB = *(const float4*)(g_PW + (int)scB.y * EDGE_C + 4 * lane);

#pragma unroll
    for (int p = 0; p < EDGES_PER_WARP / 2; p++) {
        const size_t edge = e0 + 2 * p;
        // prefetch next pair's scalars early
        float4 nscA, nscB;
        if (p < EDGES_PER_WARP / 2 - 1) {
            nscA = g_E4[edge + 2];
            nscB = g_E4[edge + 3];
        }

        float ttA = (scA.x - mu_r) * (1.f / 1.25f);
        float ttB = (scB.x - mu_r) * (1.f / 1.25f);
        float rbfA = expf(-ttA * ttA);
        float rbfB = expf(-ttB * ttB);

        unsigned long long accA0 = pk2(fmaf(scA.z, w3.x, pwA.x), fmaf(scA.z, w3.y, pwA.y));
        unsigned long long accA1 = pk2(fmaf(scA.z, w3.z, pwA.z), fmaf(scA.z, w3.w, pwA.w));
        unsigned long long accB0 = pk2(fmaf(scB.z, w3.x, pwB.x), fmaf(scB.z, w3.y, pwB.y));
        unsigned long long accB1 = pk2(fmaf(scB.z, w3.z, pwB.z), fmaf(scB.z, w3.w, pwB.w));
#pragma unroll
        for (int r = 0; r < NRBF; r++) {
            float ra = __shfl_sync(0xffffffffu, rbfA, r);
            float rb = __shfl_sync(0xffffffffu, rbfB, r);
            unsigned long long ra2 = pk2(ra, ra);
            unsigned long long rb2 = pk2(rb, rb);
            accA0 = fma2(ra2, w2a[r], accA0);
            accA1 = fma2(ra2, w2b[r], accA1);
            accB0 = fma2(rb2, w2a[r], accB0);
            accB1 = fma2(rb2, w2b[r], accB1);
        }

        // prefetch next pair's PW rows (dc now known) under the reductions
        float4 npwA, npwB;
        if (p < EDGES_PER_WARP / 2 - 1) {
            npwA = *(const float4*)(g_PW + (int)nscA.y * EDGE_C + 4 * lane);
            npwB = *(const float4*)(g_PW + (int)nscB.y * EDGE_C + 4 * lane);
        }

        float a0, a1, a2, a3, b0, b1, b2, b3;
        unpk2(accA0, a0, a1); unpk2(accA1, a2, a3);
        unpk2(accB0, b0, b1); unpk2(accB1, b2, b3);

        float s1A = (a0 + a1) + (a2 + a3);
        float s1B = (b0 + b1) + (b2 + b3);
#pragma unroll
        for (int o = 16; o; o >>= 1) {
            s1A += __shfl_xor_sync(0xffffffffu, s1A, o);
            s1B += __shfl_xor_sync(0xffffffffu, s1B, o);
        }
        float meanA = s1A * (1.f / 128.f);
        float meanB = s1B * (1.f / 128.f);
        float dA0 = a0 - meanA, dA1 = a1 - meanA, dA2 = a2 - meanA, dA3 = a3 - meanA;
        float dB0 = b0 - meanB, dB1 = b1 - meanB, dB2 = b2 - meanB, dB3 = b3 - meanB;
        float s2A = (dA0 * dA0 + dA1 * dA1) + (dA2 * dA2 + dA3 * dA3);
        float s2B = (dB0 * dB0 + dB1 * dB1) + (dB2 * dB2 + dB3 * dB3);
#pragma unroll
        for (int o = 16; o; o >>= 1) {
            s2A += __shfl_xor_sync(0xffffffffu, s2A, o);
            s2B += __shfl_xor_sync(0xffffffffu, s2B, o);
        }
        float rstdA = rsqrtf(s2A * (1.f / 128.f) + 1e-5f);
        float rstdB = rsqrtf(s2B * (1.f / 128.f) + 1e-5f);

        float4 oA, oB;
        oA.x = dA0 * rstdA * lg.x + lb.x;
        oA.y = dA1 * rstdA * lg.y + lb.y;
        oA.z = dA2 * rstdA * lg.z + lb.z;
        oA.w = dA3 * rstdA * lg.w + lb.w;
        oB.x = dB0 * rstdB * lg.x + lb.x;
        oB.y = dB1 * rstdB * lg.y + lb.y;
        oB.z = dB2 * rstdB * lg.z + lb.z;
        oB.w = dB3 * rstdB * lg.w + lb.w;
        *(float4*)(outE + (edge)     * EDGE_C + 4 * lane) = oA;
        *(float4*)(outE + (edge + 1) * EDGE_C + 4 * lane) = oB;

        scA = nscA; scB = nscB; pwA = npwA; pwB = npwB;
    }
}

// ---------------------------------------------------------------------------
extern "C" void kernel_launch(void* const* d_in, const int* in_sizes, int n_in,
                              void* d_out, int out_size) {
    const float* coords = (const float*)d_in[0];
    const float* mask   = (const float*)d_in[1];
    const float* bonds  = (const float*)d_in[2];
    const float* pe_w   = (const float*)d_in[3];
    const float* pe_b   = (const float*)d_in[4];
    const float* edge_w = (const float*)d_in[5];
    const float* ln_g   = (const float*)d_in[6];
    const float* ln_b   = (const float*)d_in[7];
    const int*   t2c    = (const int*)d_in[8];
    const int*   resi   = (const int*)d_in[9];
    // d_in[10] = asym_id (unused: chain labels forced to zero in reference)
    const int*   lig    = (const int*)d_in[11];

    float* out    = (float*)d_out;
    float* outE   = out;                                        // B*N*K*128
    float* outIdx = out + (size_t)BB * NN * KNN * EDGE_C;       // B*N*K
    float* outD   = outIdx + (size_t)BB * NN * KNN;             // B*N*K

    setup_kernel<<<32 + (PE_IN + 1) / 2, 256>>>(coords, mask, t2c, pe_w, pe_b, edge_w);
    knn_kernel<<<BB * NN / ROWS_PER_CTA, 256>>>(bonds, resi, lig, outIdx, outD);
    edge_kernel<<<BB * NN * KNN / (8 * EDGES_PER_WARP), 256>>>(edge_w, ln_g, ln_b, outE);
}